// round 15
// baseline (speedup 1.0000x reference)
#include <cuda_runtime.h>
#include <cuda_bf16.h>
#include <cstdint>
#include <math.h>

#define BB   32
#define TT_  2048
#define CIN  80
#define HCH  256
#define KTOT 240            // real K = CIN*3 ; padded to 256 in g_xk layout

// scratch (device globals: no allocation allowed)
__device__ float          g_y[TT_*BB*HCH];                 // conv out (T,B,H), 64MB
__device__ unsigned short g_xk[3u*BB*256u*TT_];            // pre-shifted im2col limbs [l][b][kl(256)][t]
__device__ __align__(16) unsigned int g_wf2[98304];        // w fragment images [hh][kst16][nf16][l3][lane][r]
__device__ double g_sum[HCH];
__device__ double g_sumsq[HCH];
__device__ float  g_mean[HCH];
__device__ float  g_rs[HCH];
__device__ unsigned int g_cnt;

__device__ __forceinline__ uint32_t smem_u32(const void* p){
    uint32_t a; asm("{ .reg .u64 t; cvta.to.shared.u64 t, %1; cvt.u32.u64 %0, t; }" : "=r"(a) : "l"(p));
    return a;
}
__device__ __forceinline__ void lds64(uint32_t* r, uint32_t addr){
    asm volatile("ld.shared.v2.b32 {%0,%1}, [%2];" : "=r"(r[0]), "=r"(r[1]) : "r"(addr));
}
#define LDSM4T(r, a) \
    asm volatile("ldmatrix.sync.aligned.m8n8.x4.trans.shared.b16 {%0,%1,%2,%3}, [%4];" \
        : "=r"((r)[0]), "=r"((r)[1]), "=r"((r)[2]), "=r"((r)[3]) : "r"(a))
__device__ __forceinline__ void mma_bf16(float* c, const uint32_t* a, const uint32_t* b){
    asm volatile("mma.sync.aligned.m16n8k16.row.col.f32.bf16.bf16.f32 "
        "{%0,%1,%2,%3}, {%4,%5,%6,%7}, {%8,%9}, {%0,%1,%2,%3};"
        : "+f"(c[0]), "+f"(c[1]), "+f"(c[2]), "+f"(c[3])
        : "r"(a[0]), "r"(a[1]), "r"(a[2]), "r"(a[3]), "r"(b[0]), "r"(b[1]));
}
__device__ __forceinline__ void cpa16(uint32_t dst, const void* src){
    asm volatile("cp.async.cg.shared.global [%0], [%1], 16;" :: "r"(dst), "l"(src) : "memory");
}
#define CPA_COMMIT() asm volatile("cp.async.commit_group;" ::: "memory")
#define CPA_WAIT1()  asm volatile("cp.async.wait_group 1;" ::: "memory")
#define CPA_WAIT0()  asm volatile("cp.async.wait_group 0;" ::: "memory")

__device__ __forceinline__ unsigned short bsplit(float x, int s){
    __nv_bfloat16 b0 = __float2bfloat16(x);
    if (s == 0) return __bfloat16_as_ushort(b0);
    float r1 = x - __bfloat162float(b0);
    __nv_bfloat16 b1 = __float2bfloat16(r1);
    if (s == 1) return __bfloat16_as_ushort(b1);
    float r2 = r1 - __bfloat162float(b1);
    return __bfloat16_as_ushort(__float2bfloat16(r2));
}

// ---------------- prep: x -> pre-shifted im2col bf16 limb tensor ----------------
__global__ void prep_x_kernel(const float* __restrict__ x){
    extern __shared__ unsigned short sl[];   // [3][80][132]
    const int b = blockIdx.y, t0 = blockIdx.x*128, tid = threadIdx.x;
    for (int i = tid; i < 131*CIN; i += 256){
        int p = i/CIN, c = i - p*CIN;
        int t = t0 - 1 + p;
        float v = (t >= 0 && t < TT_) ? x[((size_t)b*TT_ + t)*CIN + c] : 0.f;
        __nv_bfloat16 l0 = __float2bfloat16(v);
        float r1 = v - __bfloat162float(l0);
        __nv_bfloat16 l1 = __float2bfloat16(r1);
        float r2 = r1 - __bfloat162float(l1);
        __nv_bfloat16 l2 = __float2bfloat16(r2);
        sl[(0*CIN + c)*132 + p] = __bfloat16_as_ushort(l0);
        sl[(1*CIN + c)*132 + p] = __bfloat16_as_ushort(l1);
        sl[(2*CIN + c)*132 + p] = __bfloat16_as_ushort(l2);
    }
    __syncthreads();
    uint32_t* dst = (uint32_t*)g_xk;
    for (int i = tid; i < 3*256*64; i += 256){
        int j2 = i & 63, row = i >> 6;
        int l = row >> 8, klr = row & 255;
        uint32_t vv = 0;
        if (klr < KTOT){
            int c = (klr*171) >> 9, kk = klr - 3*c;
            int base = (l*CIN + c)*132 + kk;
            uint32_t v0 = sl[base + 2*j2];
            uint32_t v1 = sl[base + 2*j2 + 1];
            vv = v0 | (v1 << 16);
        }
        dst[((size_t)(l*BB + b)*256 + klr)*1024 + (t0 >> 1) + j2] = vv;
    }
}

// ---------------- prep: w -> fragment images (kst-major), zero BN accumulators ----------------
__global__ void prep_w_kernel(const float* __restrict__ w){
    int i = blockIdx.x*256 + threadIdx.x;
    if (i < HCH){ g_sum[i] = 0.0; g_sumsq[i] = 0.0; }
    if (i == 0) g_cnt = 0u;
    if (i >= 98304) return;
    int r    = i & 1;
    int lane = (i >> 1) & 31;
    int rest = i >> 6;
    int l   = rest % 3;  rest /= 3;
    int nf  = rest & 15; rest >>= 4;
    int kst = rest & 15;
    int hh  = rest >> 4;
    uint32_t vv = 0;
    if (kst < 15){
        int n  = hh*128 + nf*8 + (lane >> 2);
        int k0 = kst*16 + (lane & 3)*2 + r*8;
        int c0 = (k0*171) >> 9, kk0 = k0 - 3*c0;
        int k1 = k0 + 1;
        int c1 = (k1*171) >> 9, kk1 = k1 - 3*c1;
        uint32_t v0 = bsplit(w[(size_t)n*KTOT + c0*3 + kk0], l);
        uint32_t v1 = bsplit(w[(size_t)n*KTOT + c1*3 + kk1], l);
        vv = v0 | (v1 << 16);
    }
    g_wf2[i] = vv;
}

// ---------------- conv via mma.sync bf16 6-GEMM (verbatim R9) ----------------
#define ABUF 26112u          // 3 limbs * 32 rows * 272B
#define BBUF 24576u          // 2 ks * 16 nf * 3 l * 256B
#define BBASE (2u*ABUF)      // 52224
#define SMEM_CONV (BBASE + 2*BBUF)   // 101376

__global__ void __launch_bounds__(512, 1) conv_mma_kernel(const float* __restrict__ bias){
    extern __shared__ char smem[];
    const uint32_t sb = smem_u32(smem);
    const int tid = threadIdx.x, lane = tid & 31, w = tid >> 5;
    const int wm = w >> 2, wn = w & 3;
    const int t0 = blockIdx.x * 128;
    const int hh = blockIdx.y;
    const int b  = blockIdx.z;

    float acc[2][4][4];
    #pragma unroll
    for (int mf = 0; mf < 2; ++mf)
        #pragma unroll
        for (int nf = 0; nf < 4; ++nf)
            #pragma unroll
            for (int q = 0; q < 4; ++q) acc[mf][nf][q] = 0.f;

    const uint32_t laneA = ((((lane >> 4) << 3) | (lane & 7)) * 272u)
                         + (uint32_t)(wm*32 + ((lane >> 3) & 1)*8) * 2u;

    auto prefetch = [&](int c, int buf){
        #pragma unroll
        for (int k = 0; k < 3; ++k){
            int j = tid + k*512;
            int row = j >> 4, seg = j & 15;
            int l = row >> 5, klr = row & 31;
            const char* src = (const char*)g_xk
                + (((((size_t)l*BB + b)*256 + (c*32 + klr))*2048 + t0) << 1) + seg*16;
            cpa16(sb + (uint32_t)buf*ABUF + (uint32_t)l*8704u + (uint32_t)klr*272u + (uint32_t)seg*16u, src);
        }
        const char* bs = (const char*)g_wf2 + (size_t)(hh*16 + c*2)*12288u;
        #pragma unroll
        for (int k = 0; k < 3; ++k){
            int j = tid + k*512;
            cpa16(sb + BBASE + (uint32_t)buf*BBUF + (uint32_t)j*16u, bs + (size_t)j*16);
        }
        CPA_COMMIT();
    };

    auto kstep = [&](int ks, uint32_t aT, uint32_t bT){
        uint32_t A0[2][4], A1[2][4], A2[2][4], B0[4][2], B1[4][2], B2[4][2];
        #pragma unroll
        for (int mf = 0; mf < 2; ++mf){
            uint32_t a = aT + (uint32_t)ks*4352u + (uint32_t)mf*32u;
            LDSM4T(A0[mf], a);
            LDSM4T(A1[mf], a + 8704u);
            LDSM4T(A2[mf], a + 17408u);
        }
        #pragma unroll
        for (int nf = 0; nf < 4; ++nf){
            uint32_t ba = bT + (uint32_t)(ks*48 + nf*3)*256u;
            lds64(B0[nf], ba);
            lds64(B1[nf], ba + 256u);
            lds64(B2[nf], ba + 512u);
        }
        // per-accumulator limb pass order (bitwise-stable): 00,01,10,11,02,20
        #pragma unroll
        for (int mf = 0; mf < 2; ++mf)
            #pragma unroll
            for (int nf = 0; nf < 4; ++nf){
                mma_bf16(acc[mf][nf], A0[mf], B0[nf]);
                mma_bf16(acc[mf][nf], A0[mf], B1[nf]);
                mma_bf16(acc[mf][nf], A1[mf], B0[nf]);
                mma_bf16(acc[mf][nf], A1[mf], B1[nf]);
                mma_bf16(acc[mf][nf], A0[mf], B2[nf]);
                mma_bf16(acc[mf][nf], A2[mf], B0[nf]);
            }
    };

    prefetch(0, 0);
    for (int c = 0; c < 8; ++c){
        const int buf = c & 1;
        if (c < 7){ prefetch(c+1, buf^1); CPA_WAIT1(); } else { CPA_WAIT0(); }
        __syncthreads();
        const uint32_t aT = sb + (uint32_t)buf*ABUF + laneA;
        const uint32_t bT = sb + BBASE + (uint32_t)buf*BBUF + (uint32_t)(wn*12)*256u + (uint32_t)lane*8u;
        kstep(0, aT, bT);
        if (c < 7) kstep(1, aT, bT);   // kst 15 (k 240..255) is zero padding — skip
        __syncthreads();
    }

    // epilogue: acc + bias -> g_y (numerics unchanged)
    const int rbase = t0 + wm*32;
    const int hbase = hh*128 + wn*32;
    #pragma unroll
    for (int mf = 0; mf < 2; ++mf){
        int m0 = rbase + mf*16 + (lane >> 2);
        #pragma unroll
        for (int nf = 0; nf < 4; ++nf){
            int n = hbase + nf*8 + (lane & 3)*2;
            float2 bv = *(const float2*)(bias + n);
            float2 o0 = make_float2(acc[mf][nf][0] + bv.x, acc[mf][nf][1] + bv.y);
            float2 o1 = make_float2(acc[mf][nf][2] + bv.x, acc[mf][nf][3] + bv.y);
            *(float2*)(g_y + ((size_t)m0*BB + b)*HCH + n)     = o0;
            *(float2*)(g_y + ((size_t)(m0+8)*BB + b)*HCH + n) = o1;
        }
    }
}

// ---------------- BN stats: float4 loads, shfl combine, last-block finalize ----------------
// grid 512, block 256. Thread owns h = (tid>>2)*4..+3, rows rsub, rsub+4, ..., rsub+124.
__global__ void bn_stats_kernel(){
    const int tid  = threadIdx.x;
    const int rsub = tid & 3;
    const int h4   = tid >> 2;          // 0..63
    const size_t r0 = (size_t)blockIdx.x * 128;
    const float4* yp = (const float4*)(g_y + (r0 + rsub)*HCH) + h4;

    float s0=0,s1=0,s2=0,s3=0, q0=0,q1=0,q2=0,q3=0;
    float4 v[8], nx[8];
    #pragma unroll
    for (int j = 0; j < 8; ++j) v[j] = yp[(size_t)j*256];     // stride = 4 rows
    for (int ii = 0; ii < 32; ii += 8){
        if (ii < 24){
            #pragma unroll
            for (int j = 0; j < 8; ++j) nx[j] = yp[(size_t)(ii + 8 + j)*256];
        }
        #pragma unroll
        for (int j = 0; j < 8; ++j){
            s0 += v[j].x; q0 += v[j].x*v[j].x;
            s1 += v[j].y; q1 += v[j].y*v[j].y;
            s2 += v[j].z; q2 += v[j].z*v[j].z;
            s3 += v[j].w; q3 += v[j].w*v[j].w;
        }
        #pragma unroll
        for (int j = 0; j < 8; ++j) v[j] = nx[j];
    }
    // combine the 4-thread row split (lanes differing in bits 0-1 share h)
    #pragma unroll
    for (int d = 1; d < 4; d <<= 1){
        s0 += __shfl_xor_sync(0xffffffffu, s0, d); q0 += __shfl_xor_sync(0xffffffffu, q0, d);
        s1 += __shfl_xor_sync(0xffffffffu, s1, d); q1 += __shfl_xor_sync(0xffffffffu, q1, d);
        s2 += __shfl_xor_sync(0xffffffffu, s2, d); q2 += __shfl_xor_sync(0xffffffffu, q2, d);
        s3 += __shfl_xor_sync(0xffffffffu, s3, d); q3 += __shfl_xor_sync(0xffffffffu, q3, d);
    }
    if (rsub == 0){
        int h = h4*4;
        atomicAdd(&g_sum[h+0], (double)s0); atomicAdd(&g_sumsq[h+0], (double)q0);
        atomicAdd(&g_sum[h+1], (double)s1); atomicAdd(&g_sumsq[h+1], (double)q1);
        atomicAdd(&g_sum[h+2], (double)s2); atomicAdd(&g_sumsq[h+2], (double)q2);
        atomicAdd(&g_sum[h+3], (double)s3); atomicAdd(&g_sumsq[h+3], (double)q3);
    }
    // last CTA computes mean/rsqrt (identical double formula as before)
    __threadfence();
    __syncthreads();
    __shared__ unsigned int s_last;
    if (tid == 0) s_last = atomicAdd(&g_cnt, 1u);
    __syncthreads();
    if (s_last == (unsigned)(gridDim.x - 1)){
        for (int h = tid; h < HCH; h += 256){
            double su = *((volatile double*)&g_sum[h]);
            double sq = *((volatile double*)&g_sumsq[h]);
            const double nn = (double)(TT_*BB);
            double mu  = su / nn;
            double var = sq / nn - mu*mu;
            g_mean[h] = (float)mu;
            g_rs[h]   = (float)(1.0 / sqrt(var + 1e-5));
        }
    }
}

// ---------------- LIF recurrence (verbatim R9) ----------------
#define CHUNK 128
#define WARM  96
#define NCHUNK (TT_/CHUNK)
__global__ void __launch_bounds__(256) lif_kernel(const float* __restrict__ gamma,
                                                  const float* __restrict__ beta,
                                                  float* __restrict__ out){
    int g    = blockIdx.x*256 + threadIdx.x;
    int lane = g & (BB*HCH - 1);
    int chunk = g >> 13;
    int h = lane & 255;

    float mu = g_mean[h], rs = g_rs[h], ga = gamma[h], be = beta[h];
    int tstart = chunk * CHUNK;
    int tw = (chunk == 0) ? 0 : tstart - WARM;
    int tend = tstart + CHUNK;

    const float* yp = g_y + lane;
    float* op = out + lane;
    float v = 0.f;

    float cur[16], nxt[16];
    #pragma unroll
    for (int j = 0; j < 16; ++j) cur[j] = yp[(size_t)(tw + j)*(BB*HCH)];

    for (int t0v = tw; t0v < tend; t0v += 16){
        int tn = t0v + 16;
        if (tn < tend){
            #pragma unroll
            for (int j = 0; j < 16; ++j) nxt[j] = yp[(size_t)(tn + j)*(BB*HCH)];
        }
        bool do_store = (t0v >= tstart);
        #pragma unroll
        for (int j = 0; j < 16; ++j){
            float yn = fmaf((cur[j] - mu)*rs, ga, be);
            v = fmaf(v, 0.5f, yn);
            bool sp = (v >= 1.0f);
            if (do_store) op[(size_t)(t0v + j)*(BB*HCH)] = sp ? 1.0f : 0.0f;
            v = sp ? 0.0f : v;
        }
        #pragma unroll
        for (int j = 0; j < 16; ++j) cur[j] = nxt[j];
    }
}

extern "C" void kernel_launch(void* const* d_in, const int* in_sizes, int n_in,
                              void* d_out, int out_size){
    const float* x     = (const float*)d_in[0];
    const float* w     = (const float*)d_in[1];
    const float* bias  = (const float*)d_in[2];
    const float* gamma = (const float*)d_in[3];
    const float* beta  = (const float*)d_in[4];
    float* out = (float*)d_out;

    cudaFuncSetAttribute(prep_x_kernel, cudaFuncAttributeMaxDynamicSharedMemorySize, 3*CIN*132*2);
    cudaFuncSetAttribute(conv_mma_kernel, cudaFuncAttributeMaxDynamicSharedMemorySize, SMEM_CONV);

    prep_x_kernel<<<dim3(TT_/128, BB), 256, 3*CIN*132*2>>>(x);
    prep_w_kernel<<<384, 256>>>(w);
    conv_mma_kernel<<<dim3(TT_/128, 2, BB), 512, SMEM_CONV>>>(bias);
    bn_stats_kernel<<<512, 256>>>();
    lif_kernel<<<(BB*HCH*NCHUNK)/256, 256>>>(gamma, beta, out);
}

// round 16
// speedup vs baseline: 1.0419x; 1.0419x over previous
#include <cuda_runtime.h>
#include <cuda_bf16.h>
#include <cstdint>
#include <math.h>

#define BB   32
#define TT_  2048
#define CIN  80
#define HCH  256
#define KTOT 240            // real K = CIN*3 ; padded to 256 in g_xk layout

// scratch (device globals: no allocation allowed)
__device__ float          g_y[TT_*BB*HCH];                 // conv out (T,B,H), 64MB
__device__ unsigned short g_xk[3u*BB*256u*TT_];            // pre-shifted im2col limbs [l][b][kl(256)][t]
__device__ __align__(16) unsigned int g_wf2[98304];        // w fragment images [hh][kst16][nf16][l3][lane][r]
__device__ double g_sum[HCH];
__device__ double g_sumsq[HCH];
__device__ float  g_mean[HCH];
__device__ float  g_rs[HCH];
__device__ unsigned int g_cnt;

__device__ __forceinline__ uint32_t smem_u32(const void* p){
    uint32_t a; asm("{ .reg .u64 t; cvta.to.shared.u64 t, %1; cvt.u32.u64 %0, t; }" : "=r"(a) : "l"(p));
    return a;
}
__device__ __forceinline__ void lds64(uint32_t* r, uint32_t addr){
    asm volatile("ld.shared.v2.b32 {%0,%1}, [%2];" : "=r"(r[0]), "=r"(r[1]) : "r"(addr));
}
#define LDSM4T(r, a) \
    asm volatile("ldmatrix.sync.aligned.m8n8.x4.trans.shared.b16 {%0,%1,%2,%3}, [%4];" \
        : "=r"((r)[0]), "=r"((r)[1]), "=r"((r)[2]), "=r"((r)[3]) : "r"(a))
__device__ __forceinline__ void mma_bf16(float* c, const uint32_t* a, const uint32_t* b){
    asm volatile("mma.sync.aligned.m16n8k16.row.col.f32.bf16.bf16.f32 "
        "{%0,%1,%2,%3}, {%4,%5,%6,%7}, {%8,%9}, {%0,%1,%2,%3};"
        : "+f"(c[0]), "+f"(c[1]), "+f"(c[2]), "+f"(c[3])
        : "r"(a[0]), "r"(a[1]), "r"(a[2]), "r"(a[3]), "r"(b[0]), "r"(b[1]));
}
__device__ __forceinline__ void cpa16(uint32_t dst, const void* src){
    asm volatile("cp.async.cg.shared.global [%0], [%1], 16;" :: "r"(dst), "l"(src) : "memory");
}
#define CPA_COMMIT() asm volatile("cp.async.commit_group;" ::: "memory")
#define CPA_WAIT1()  asm volatile("cp.async.wait_group 1;" ::: "memory")
#define CPA_WAIT0()  asm volatile("cp.async.wait_group 0;" ::: "memory")

__device__ __forceinline__ unsigned short bsplit(float x, int s){
    __nv_bfloat16 b0 = __float2bfloat16(x);
    if (s == 0) return __bfloat16_as_ushort(b0);
    float r1 = x - __bfloat162float(b0);
    __nv_bfloat16 b1 = __float2bfloat16(r1);
    if (s == 1) return __bfloat16_as_ushort(b1);
    float r2 = r1 - __bfloat162float(b1);
    return __bfloat16_as_ushort(__float2bfloat16(r2));
}

// ---------------- prep: x -> pre-shifted im2col bf16 limb tensor ----------------
__global__ void prep_x_kernel(const float* __restrict__ x){
    extern __shared__ unsigned short sl[];   // [3][80][132]
    const int b = blockIdx.y, t0 = blockIdx.x*128, tid = threadIdx.x;
    for (int i = tid; i < 131*CIN; i += 256){
        int p = i/CIN, c = i - p*CIN;
        int t = t0 - 1 + p;
        float v = (t >= 0 && t < TT_) ? x[((size_t)b*TT_ + t)*CIN + c] : 0.f;
        __nv_bfloat16 l0 = __float2bfloat16(v);
        float r1 = v - __bfloat162float(l0);
        __nv_bfloat16 l1 = __float2bfloat16(r1);
        float r2 = r1 - __bfloat162float(l1);
        __nv_bfloat16 l2 = __float2bfloat16(r2);
        sl[(0*CIN + c)*132 + p] = __bfloat16_as_ushort(l0);
        sl[(1*CIN + c)*132 + p] = __bfloat16_as_ushort(l1);
        sl[(2*CIN + c)*132 + p] = __bfloat16_as_ushort(l2);
    }
    __syncthreads();
    uint32_t* dst = (uint32_t*)g_xk;
    for (int i = tid; i < 3*256*64; i += 256){
        int j2 = i & 63, row = i >> 6;
        int l = row >> 8, klr = row & 255;
        uint32_t vv = 0;
        if (klr < KTOT){
            int c = (klr*171) >> 9, kk = klr - 3*c;
            int base = (l*CIN + c)*132 + kk;
            uint32_t v0 = sl[base + 2*j2];
            uint32_t v1 = sl[base + 2*j2 + 1];
            vv = v0 | (v1 << 16);
        }
        dst[((size_t)(l*BB + b)*256 + klr)*1024 + (t0 >> 1) + j2] = vv;
    }
}

// ---------------- prep: w -> fragment images (kst-major), zero BN accumulators ----------------
__global__ void prep_w_kernel(const float* __restrict__ w){
    int i = blockIdx.x*256 + threadIdx.x;
    if (i < HCH){ g_sum[i] = 0.0; g_sumsq[i] = 0.0; }
    if (i == 0) g_cnt = 0u;
    if (i >= 98304) return;
    int r    = i & 1;
    int lane = (i >> 1) & 31;
    int rest = i >> 6;
    int l   = rest % 3;  rest /= 3;
    int nf  = rest & 15; rest >>= 4;
    int kst = rest & 15;
    int hh  = rest >> 4;
    uint32_t vv = 0;
    if (kst < 15){
        int n  = hh*128 + nf*8 + (lane >> 2);
        int k0 = kst*16 + (lane & 3)*2 + r*8;
        int c0 = (k0*171) >> 9, kk0 = k0 - 3*c0;
        int k1 = k0 + 1;
        int c1 = (k1*171) >> 9, kk1 = k1 - 3*c1;
        uint32_t v0 = bsplit(w[(size_t)n*KTOT + c0*3 + kk0], l);
        uint32_t v1 = bsplit(w[(size_t)n*KTOT + c1*3 + kk1], l);
        vv = v0 | (v1 << 16);
    }
    g_wf2[i] = vv;
}

// ---------------- conv via mma.sync bf16 6-GEMM + fused atomic-free BN stats ----------------
#define ABUF 26112u          // 3 limbs * 32 rows * 272B
#define BBUF 24576u          // 2 ks * 16 nf * 3 l * 256B
#define BBASE (2u*ABUF)      // 52224
#define SMEM_CONV (BBASE + 2*BBUF)   // 101376
#define NCTA_CONV (16*2*32)  // 1024

__global__ void __launch_bounds__(512, 1) conv_mma_kernel(const float* __restrict__ bias){
    extern __shared__ char smem[];
    const uint32_t sb = smem_u32(smem);
    const int tid = threadIdx.x, lane = tid & 31, w = tid >> 5;
    const int wm = w >> 2, wn = w & 3;
    const int t0 = blockIdx.x * 128;
    const int hh = blockIdx.y;
    const int b  = blockIdx.z;

    float acc[2][4][4];
    #pragma unroll
    for (int mf = 0; mf < 2; ++mf)
        #pragma unroll
        for (int nf = 0; nf < 4; ++nf)
            #pragma unroll
            for (int q = 0; q < 4; ++q) acc[mf][nf][q] = 0.f;

    const uint32_t laneA = ((((lane >> 4) << 3) | (lane & 7)) * 272u)
                         + (uint32_t)(wm*32 + ((lane >> 3) & 1)*8) * 2u;

    auto prefetch = [&](int c, int buf){
        #pragma unroll
        for (int k = 0; k < 3; ++k){
            int j = tid + k*512;
            int row = j >> 4, seg = j & 15;
            int l = row >> 5, klr = row & 31;
            const char* src = (const char*)g_xk
                + (((((size_t)l*BB + b)*256 + (c*32 + klr))*2048 + t0) << 1) + seg*16;
            cpa16(sb + (uint32_t)buf*ABUF + (uint32_t)l*8704u + (uint32_t)klr*272u + (uint32_t)seg*16u, src);
        }
        const char* bs = (const char*)g_wf2 + (size_t)(hh*16 + c*2)*12288u;
        #pragma unroll
        for (int k = 0; k < 3; ++k){
            int j = tid + k*512;
            cpa16(sb + BBASE + (uint32_t)buf*BBUF + (uint32_t)j*16u, bs + (size_t)j*16);
        }
        CPA_COMMIT();
    };

    auto kstep = [&](int ks, uint32_t aT, uint32_t bT){
        uint32_t A0[2][4], A1[2][4], A2[2][4], B0[4][2], B1[4][2], B2[4][2];
        #pragma unroll
        for (int mf = 0; mf < 2; ++mf){
            uint32_t a = aT + (uint32_t)ks*4352u + (uint32_t)mf*32u;
            LDSM4T(A0[mf], a);
            LDSM4T(A1[mf], a + 8704u);
            LDSM4T(A2[mf], a + 17408u);
        }
        #pragma unroll
        for (int nf = 0; nf < 4; ++nf){
            uint32_t ba = bT + (uint32_t)(ks*48 + nf*3)*256u;
            lds64(B0[nf], ba);
            lds64(B1[nf], ba + 256u);
            lds64(B2[nf], ba + 512u);
        }
        // per-accumulator limb pass order (bitwise-stable): 00,01,10,11,02,20
        #pragma unroll
        for (int mf = 0; mf < 2; ++mf)
            #pragma unroll
            for (int nf = 0; nf < 4; ++nf){
                mma_bf16(acc[mf][nf], A0[mf], B0[nf]);
                mma_bf16(acc[mf][nf], A0[mf], B1[nf]);
                mma_bf16(acc[mf][nf], A1[mf], B0[nf]);
                mma_bf16(acc[mf][nf], A1[mf], B1[nf]);
                mma_bf16(acc[mf][nf], A0[mf], B2[nf]);
                mma_bf16(acc[mf][nf], A2[mf], B0[nf]);
            }
    };

    prefetch(0, 0);
    for (int c = 0; c < 8; ++c){
        const int buf = c & 1;
        if (c < 7){ prefetch(c+1, buf^1); CPA_WAIT1(); } else { CPA_WAIT0(); }
        __syncthreads();
        const uint32_t aT = sb + (uint32_t)buf*ABUF + laneA;
        const uint32_t bT = sb + BBASE + (uint32_t)buf*BBUF + (uint32_t)(wn*12)*256u + (uint32_t)lane*8u;
        kstep(0, aT, bT);
        if (c < 7) kstep(1, aT, bT);   // kst 15 (k 240..255) is zero padding — skip
        __syncthreads();
    }

    // ---- epilogue: acc + bias -> g_y (bitwise-unchanged) + per-thread stat partials ----
    float sp[4][2], qp[4][2];
    const int rbase = t0 + wm*32;
    const int hbase = hh*128 + wn*32;
    #pragma unroll
    for (int nf = 0; nf < 4; ++nf){ sp[nf][0]=0.f; sp[nf][1]=0.f; qp[nf][0]=0.f; qp[nf][1]=0.f; }
    #pragma unroll
    for (int mf = 0; mf < 2; ++mf){
        int m0 = rbase + mf*16 + (lane >> 2);
        #pragma unroll
        for (int nf = 0; nf < 4; ++nf){
            int n = hbase + nf*8 + (lane & 3)*2;
            float2 bv = *(const float2*)(bias + n);
            float2 o0 = make_float2(acc[mf][nf][0] + bv.x, acc[mf][nf][1] + bv.y);
            float2 o1 = make_float2(acc[mf][nf][2] + bv.x, acc[mf][nf][3] + bv.y);
            *(float2*)(g_y + ((size_t)m0*BB + b)*HCH + n)     = o0;
            *(float2*)(g_y + ((size_t)(m0+8)*BB + b)*HCH + n) = o1;
            sp[nf][0] += o0.x; sp[nf][0] += o1.x;   qp[nf][0] += o0.x*o0.x; qp[nf][0] += o1.x*o1.x;
            sp[nf][1] += o0.y; sp[nf][1] += o1.y;   qp[nf][1] += o0.y*o0.y; qp[nf][1] += o1.y*o1.y;
        }
    }
    // warp reduce over row-groups (lanes sharing lane&3 hold same h-slots)
    #pragma unroll
    for (int nf = 0; nf < 4; ++nf)
        #pragma unroll
        for (int e = 0; e < 2; ++e)
            #pragma unroll
            for (int d = 4; d < 32; d <<= 1){
                sp[nf][e] += __shfl_xor_sync(0xffffffffu, sp[nf][e], d);
                qp[nf][e] += __shfl_xor_sync(0xffffffffu, qp[nf][e], d);
            }
    // plain smem staging: [wm][wn][32 h_local], sums then sumsq (A/B buffers are dead)
    float* sred = (float*)smem;
    float* qred = sred + 512;
    if ((lane >> 2) == 0){
        #pragma unroll
        for (int nf = 0; nf < 4; ++nf)
            #pragma unroll
            for (int e = 0; e < 2; ++e){
                int hl = nf*8 + (lane & 3)*2 + e;
                sred[(wm*4 + wn)*32 + hl] = sp[nf][e];
                qred[(wm*4 + wn)*32 + hl] = qp[nf][e];
            }
    }
    __syncthreads();
    if (tid < 128){
        int wnb = tid >> 5, hl = tid & 31;
        float s = ((sred[(0*4+wnb)*32+hl] + sred[(1*4+wnb)*32+hl]) + sred[(2*4+wnb)*32+hl]) + sred[(3*4+wnb)*32+hl];
        float q = ((qred[(0*4+wnb)*32+hl] + qred[(1*4+wnb)*32+hl]) + qred[(2*4+wnb)*32+hl]) + qred[(3*4+wnb)*32+hl];
        int h = hh*128 + wnb*32 + hl;
        atomicAdd(&g_sum[h],   (double)s);
        atomicAdd(&g_sumsq[h], (double)q);
    }
    // last-CTA BN finalize (identical double formula)
    __threadfence();
    __syncthreads();
    __shared__ unsigned int s_last;
    if (tid == 0) s_last = atomicAdd(&g_cnt, 1u);
    __syncthreads();
    if (s_last == (unsigned)(NCTA_CONV - 1)){
        if (tid < HCH){
            double su = *((volatile double*)&g_sum[tid]);
            double sq = *((volatile double*)&g_sumsq[tid]);
            const double nn = (double)(TT_*BB);
            double mu  = su / nn;
            double var = sq / nn - mu*mu;
            g_mean[tid] = (float)mu;
            g_rs[tid]   = (float)(1.0 / sqrt(var + 1e-5));
        }
    }
}

// ---------------- LIF recurrence (verbatim R9) ----------------
#define CHUNK 128
#define WARM  96
#define NCHUNK (TT_/CHUNK)
__global__ void __launch_bounds__(256) lif_kernel(const float* __restrict__ gamma,
                                                  const float* __restrict__ beta,
                                                  float* __restrict__ out){
    int g    = blockIdx.x*256 + threadIdx.x;
    int lane = g & (BB*HCH - 1);
    int chunk = g >> 13;
    int h = lane & 255;

    float mu = g_mean[h], rs = g_rs[h], ga = gamma[h], be = beta[h];
    int tstart = chunk * CHUNK;
    int tw = (chunk == 0) ? 0 : tstart - WARM;
    int tend = tstart + CHUNK;

    const float* yp = g_y + lane;
    float* op = out + lane;
    float v = 0.f;

    float cur[16], nxt[16];
    #pragma unroll
    for (int j = 0; j < 16; ++j) cur[j] = yp[(size_t)(tw + j)*(BB*HCH)];

    for (int t0v = tw; t0v < tend; t0v += 16){
        int tn = t0v + 16;
        if (tn < tend){
            #pragma unroll
            for (int j = 0; j < 16; ++j) nxt[j] = yp[(size_t)(tn + j)*(BB*HCH)];
        }
        bool do_store = (t0v >= tstart);
        #pragma unroll
        for (int j = 0; j < 16; ++j){
            float yn = fmaf((cur[j] - mu)*rs, ga, be);
            v = fmaf(v, 0.5f, yn);
            bool sp = (v >= 1.0f);
            if (do_store) op[(size_t)(t0v + j)*(BB*HCH)] = sp ? 1.0f : 0.0f;
            v = sp ? 0.0f : v;
        }
        #pragma unroll
        for (int j = 0; j < 16; ++j) cur[j] = nxt[j];
    }
}

extern "C" void kernel_launch(void* const* d_in, const int* in_sizes, int n_in,
                              void* d_out, int out_size){
    const float* x     = (const float*)d_in[0];
    const float* w     = (const float*)d_in[1];
    const float* bias  = (const float*)d_in[2];
    const float* gamma = (const float*)d_in[3];
    const float* beta  = (const float*)d_in[4];
    float* out = (float*)d_out;

    cudaFuncSetAttribute(prep_x_kernel, cudaFuncAttributeMaxDynamicSharedMemorySize, 3*CIN*132*2);
    cudaFuncSetAttribute(conv_mma_kernel, cudaFuncAttributeMaxDynamicSharedMemorySize, SMEM_CONV);

    prep_x_kernel<<<dim3(TT_/128, BB), 256, 3*CIN*132*2>>>(x);
    prep_w_kernel<<<384, 256>>>(w);
    conv_mma_kernel<<<dim3(TT_/128, 2, BB), 512, SMEM_CONV>>>(bias);
    lif_kernel<<<(BB*HCH*NCHUNK)/256, 256>>>(gamma, beta, out);
}

// round 17
// speedup vs baseline: 1.1288x; 1.0834x over previous
#include <cuda_runtime.h>
#include <cuda_bf16.h>
#include <cstdint>
#include <math.h>

#define BB   32
#define TT_  2048
#define CIN  80
#define HCH  256
#define KTOT 240            // real K = CIN*3 ; padded to 256 in g_xk layout

// scratch (device globals: no allocation allowed; zero-initialized at module load)
__device__ float          g_y[TT_*BB*HCH];                 // conv out (T,B,H), 64MB
__device__ unsigned short g_xk[3u*BB*256u*TT_];            // pre-shifted im2col limbs [l][b][kl(256)][t]
__device__ __align__(16) unsigned int g_wf2[98304];        // w fragment images [hh][kst16][nf16][l3][lane][r]
__device__ double g_sum[HCH];
__device__ double g_sumsq[HCH];
__device__ float  g_mean[HCH];
__device__ float  g_rs[HCH];
__device__ unsigned int g_cnt;

__device__ __forceinline__ uint32_t smem_u32(const void* p){
    uint32_t a; asm("{ .reg .u64 t; cvta.to.shared.u64 t, %1; cvt.u32.u64 %0, t; }" : "=r"(a) : "l"(p));
    return a;
}
__device__ __forceinline__ void lds64(uint32_t* r, uint32_t addr){
    asm volatile("ld.shared.v2.b32 {%0,%1}, [%2];" : "=r"(r[0]), "=r"(r[1]) : "r"(addr));
}
#define LDSM4T(r, a) \
    asm volatile("ldmatrix.sync.aligned.m8n8.x4.trans.shared.b16 {%0,%1,%2,%3}, [%4];" \
        : "=r"((r)[0]), "=r"((r)[1]), "=r"((r)[2]), "=r"((r)[3]) : "r"(a))
__device__ __forceinline__ void mma_bf16(float* c, const uint32_t* a, const uint32_t* b){
    asm volatile("mma.sync.aligned.m16n8k16.row.col.f32.bf16.bf16.f32 "
        "{%0,%1,%2,%3}, {%4,%5,%6,%7}, {%8,%9}, {%0,%1,%2,%3};"
        : "+f"(c[0]), "+f"(c[1]), "+f"(c[2]), "+f"(c[3])
        : "r"(a[0]), "r"(a[1]), "r"(a[2]), "r"(a[3]), "r"(b[0]), "r"(b[1]));
}
__device__ __forceinline__ void cpa16(uint32_t dst, const void* src){
    asm volatile("cp.async.cg.shared.global [%0], [%1], 16;" :: "r"(dst), "l"(src) : "memory");
}
#define CPA_COMMIT() asm volatile("cp.async.commit_group;" ::: "memory")
#define CPA_WAIT1()  asm volatile("cp.async.wait_group 1;" ::: "memory")
#define CPA_WAIT0()  asm volatile("cp.async.wait_group 0;" ::: "memory")

__device__ __forceinline__ unsigned short bsplit(float x, int s){
    __nv_bfloat16 b0 = __float2bfloat16(x);
    if (s == 0) return __bfloat16_as_ushort(b0);
    float r1 = x - __bfloat162float(b0);
    __nv_bfloat16 b1 = __float2bfloat16(r1);
    if (s == 1) return __bfloat16_as_ushort(b1);
    float r2 = r1 - __bfloat162float(b1);
    return __bfloat16_as_ushort(__float2bfloat16(r2));
}

// ---------------- prep: x -> pre-shifted im2col bf16 limb tensor ----------------
// pad rows (klr >= 240) are never written: device globals are zero-initialized
__global__ void prep_x_kernel(const float* __restrict__ x){
    extern __shared__ unsigned short sl[];   // [3][80][132]
    const int b = blockIdx.y, t0 = blockIdx.x*128, tid = threadIdx.x;
    for (int i = tid; i < 131*CIN; i += 256){
        int p = i/CIN, c = i - p*CIN;
        int t = t0 - 1 + p;
        float v = (t >= 0 && t < TT_) ? x[((size_t)b*TT_ + t)*CIN + c] : 0.f;
        __nv_bfloat16 l0 = __float2bfloat16(v);
        float r1 = v - __bfloat162float(l0);
        __nv_bfloat16 l1 = __float2bfloat16(r1);
        float r2 = r1 - __bfloat162float(l1);
        __nv_bfloat16 l2 = __float2bfloat16(r2);
        sl[(0*CIN + c)*132 + p] = __bfloat16_as_ushort(l0);
        sl[(1*CIN + c)*132 + p] = __bfloat16_as_ushort(l1);
        sl[(2*CIN + c)*132 + p] = __bfloat16_as_ushort(l2);
    }
    __syncthreads();
    uint32_t* dst = (uint32_t*)g_xk;
    for (int i = tid; i < 3*240*64; i += 256){
        int j2 = i & 63, row = i >> 6;
        int l = row / 240, klr = row - l*240;
        int c = (klr*171) >> 9, kk = klr - 3*c;
        int base = (l*CIN + c)*132 + kk;
        uint32_t v0 = sl[base + 2*j2];
        uint32_t v1 = sl[base + 2*j2 + 1];
        dst[((size_t)(l*BB + b)*256 + klr)*1024 + (t0 >> 1) + j2] = v0 | (v1 << 16);
    }
}

// ---------------- prep: w -> fragment images (kst-major), zero BN accumulators ----------------
__global__ void prep_w_kernel(const float* __restrict__ w){
    int i = blockIdx.x*256 + threadIdx.x;
    if (i < HCH){ g_sum[i] = 0.0; g_sumsq[i] = 0.0; }
    if (i == 0) g_cnt = 0u;
    if (i >= 98304) return;
    int r    = i & 1;
    int lane = (i >> 1) & 31;
    int rest = i >> 6;
    int l   = rest % 3;  rest /= 3;
    int nf  = rest & 15; rest >>= 4;
    int kst = rest & 15;
    int hh  = rest >> 4;
    uint32_t vv = 0;
    if (kst < 15){
        int n  = hh*128 + nf*8 + (lane >> 2);
        int k0 = kst*16 + (lane & 3)*2 + r*8;
        int c0 = (k0*171) >> 9, kk0 = k0 - 3*c0;
        int k1 = k0 + 1;
        int c1 = (k1*171) >> 9, kk1 = k1 - 3*c1;
        uint32_t v0 = bsplit(w[(size_t)n*KTOT + c0*3 + kk0], l);
        uint32_t v1 = bsplit(w[(size_t)n*KTOT + c1*3 + kk1], l);
        vv = v0 | (v1 << 16);
    }
    g_wf2[i] = vv;
}

// ---------------- conv via mma.sync bf16 6-GEMM (verbatim R9) ----------------
#define ABUF 26112u          // 3 limbs * 32 rows * 272B
#define BBUF 24576u          // 2 ks * 16 nf * 3 l * 256B
#define BBASE (2u*ABUF)      // 52224
#define SMEM_CONV (BBASE + 2*BBUF)   // 101376

__global__ void __launch_bounds__(512, 1) conv_mma_kernel(const float* __restrict__ bias){
    extern __shared__ char smem[];
    const uint32_t sb = smem_u32(smem);
    const int tid = threadIdx.x, lane = tid & 31, w = tid >> 5;
    const int wm = w >> 2, wn = w & 3;
    const int t0 = blockIdx.x * 128;
    const int hh = blockIdx.y;
    const int b  = blockIdx.z;

    float acc[2][4][4];
    #pragma unroll
    for (int mf = 0; mf < 2; ++mf)
        #pragma unroll
        for (int nf = 0; nf < 4; ++nf)
            #pragma unroll
            for (int q = 0; q < 4; ++q) acc[mf][nf][q] = 0.f;

    const uint32_t laneA = ((((lane >> 4) << 3) | (lane & 7)) * 272u)
                         + (uint32_t)(wm*32 + ((lane >> 3) & 1)*8) * 2u;

    auto prefetch = [&](int c, int buf){
        #pragma unroll
        for (int k = 0; k < 3; ++k){
            int j = tid + k*512;
            int row = j >> 4, seg = j & 15;
            int l = row >> 5, klr = row & 31;
            const char* src = (const char*)g_xk
                + (((((size_t)l*BB + b)*256 + (c*32 + klr))*2048 + t0) << 1) + seg*16;
            cpa16(sb + (uint32_t)buf*ABUF + (uint32_t)l*8704u + (uint32_t)klr*272u + (uint32_t)seg*16u, src);
        }
        const char* bs = (const char*)g_wf2 + (size_t)(hh*16 + c*2)*12288u;
        #pragma unroll
        for (int k = 0; k < 3; ++k){
            int j = tid + k*512;
            cpa16(sb + BBASE + (uint32_t)buf*BBUF + (uint32_t)j*16u, bs + (size_t)j*16);
        }
        CPA_COMMIT();
    };

    auto kstep = [&](int ks, uint32_t aT, uint32_t bT){
        uint32_t A0[2][4], A1[2][4], A2[2][4], B0[4][2], B1[4][2], B2[4][2];
        #pragma unroll
        for (int mf = 0; mf < 2; ++mf){
            uint32_t a = aT + (uint32_t)ks*4352u + (uint32_t)mf*32u;
            LDSM4T(A0[mf], a);
            LDSM4T(A1[mf], a + 8704u);
            LDSM4T(A2[mf], a + 17408u);
        }
        #pragma unroll
        for (int nf = 0; nf < 4; ++nf){
            uint32_t ba = bT + (uint32_t)(ks*48 + nf*3)*256u;
            lds64(B0[nf], ba);
            lds64(B1[nf], ba + 256u);
            lds64(B2[nf], ba + 512u);
        }
        // per-accumulator limb pass order (bitwise-stable): 00,01,10,11,02,20
        #pragma unroll
        for (int mf = 0; mf < 2; ++mf)
            #pragma unroll
            for (int nf = 0; nf < 4; ++nf){
                mma_bf16(acc[mf][nf], A0[mf], B0[nf]);
                mma_bf16(acc[mf][nf], A0[mf], B1[nf]);
                mma_bf16(acc[mf][nf], A1[mf], B0[nf]);
                mma_bf16(acc[mf][nf], A1[mf], B1[nf]);
                mma_bf16(acc[mf][nf], A0[mf], B2[nf]);
                mma_bf16(acc[mf][nf], A2[mf], B0[nf]);
            }
    };

    prefetch(0, 0);
    for (int c = 0; c < 8; ++c){
        const int buf = c & 1;
        if (c < 7){ prefetch(c+1, buf^1); CPA_WAIT1(); } else { CPA_WAIT0(); }
        __syncthreads();
        const uint32_t aT = sb + (uint32_t)buf*ABUF + laneA;
        const uint32_t bT = sb + BBASE + (uint32_t)buf*BBUF + (uint32_t)(wn*12)*256u + (uint32_t)lane*8u;
        kstep(0, aT, bT);
        if (c < 7) kstep(1, aT, bT);   // kst 15 (k 240..255) is zero padding — skip
        __syncthreads();
    }

    // epilogue: acc + bias -> g_y (numerics unchanged)
    const int rbase = t0 + wm*32;
    const int hbase = hh*128 + wn*32;
    #pragma unroll
    for (int mf = 0; mf < 2; ++mf){
        int m0 = rbase + mf*16 + (lane >> 2);
        #pragma unroll
        for (int nf = 0; nf < 4; ++nf){
            int n = hbase + nf*8 + (lane & 3)*2;
            float2 bv = *(const float2*)(bias + n);
            float2 o0 = make_float2(acc[mf][nf][0] + bv.x, acc[mf][nf][1] + bv.y);
            float2 o1 = make_float2(acc[mf][nf][2] + bv.x, acc[mf][nf][3] + bv.y);
            *(float2*)(g_y + ((size_t)m0*BB + b)*HCH + n)     = o0;
            *(float2*)(g_y + ((size_t)(m0+8)*BB + b)*HCH + n) = o1;
        }
    }
}

// ---------------- BN stats (verbatim R9 loop) + last-CTA finalize fold ----------------
__global__ void bn_stats_kernel(){
    int h = threadIdx.x;
    int tid = threadIdx.x;
    size_t r0 = (size_t)blockIdx.x * 128;
    const float* yp = g_y + r0*HCH + h;
    float s = 0.f, q = 0.f;
    float v[16], nx[16];
    #pragma unroll
    for (int j = 0; j < 16; ++j) v[j] = yp[(size_t)j*HCH];
    for (int ii = 0; ii < 128; ii += 16){
        if (ii < 112){
            #pragma unroll
            for (int j = 0; j < 16; ++j) nx[j] = yp[(size_t)(ii + 16 + j)*HCH];
        }
        #pragma unroll
        for (int j = 0; j < 16; ++j){ s += v[j]; q += v[j]*v[j]; }
        #pragma unroll
        for (int j = 0; j < 16; ++j) v[j] = nx[j];
    }
    atomicAdd(&g_sum[h], (double)s);
    atomicAdd(&g_sumsq[h], (double)q);

    // last-CTA finalize (identical double formula -> bitwise-same mu/rs)
    __threadfence();
    __syncthreads();
    __shared__ unsigned int s_last;
    if (tid == 0) s_last = atomicAdd(&g_cnt, 1u);
    __syncthreads();
    if (s_last == (unsigned)(gridDim.x - 1)){
        double su = *((volatile double*)&g_sum[h]);
        double sq = *((volatile double*)&g_sumsq[h]);
        const double nn = (double)(TT_*BB);
        double mu  = su / nn;
        double var = sq / nn - mu*mu;
        g_mean[h] = (float)mu;
        g_rs[h]   = (float)(1.0 / sqrt(var + 1e-5));
    }
}

// ---------------- LIF recurrence (verbatim R9) ----------------
#define CHUNK 128
#define WARM  96
#define NCHUNK (TT_/CHUNK)
__global__ void __launch_bounds__(256) lif_kernel(const float* __restrict__ gamma,
                                                  const float* __restrict__ beta,
                                                  float* __restrict__ out){
    int g    = blockIdx.x*256 + threadIdx.x;
    int lane = g & (BB*HCH - 1);
    int chunk = g >> 13;
    int h = lane & 255;

    float mu = g_mean[h], rs = g_rs[h], ga = gamma[h], be = beta[h];
    int tstart = chunk * CHUNK;
    int tw = (chunk == 0) ? 0 : tstart - WARM;
    int tend = tstart + CHUNK;

    const float* yp = g_y + lane;
    float* op = out + lane;
    float v = 0.f;

    float cur[16], nxt[16];
    #pragma unroll
    for (int j = 0; j < 16; ++j) cur[j] = yp[(size_t)(tw + j)*(BB*HCH)];

    for (int t0v = tw; t0v < tend; t0v += 16){
        int tn = t0v + 16;
        if (tn < tend){
            #pragma unroll
            for (int j = 0; j < 16; ++j) nxt[j] = yp[(size_t)(tn + j)*(BB*HCH)];
        }
        bool do_store = (t0v >= tstart);
        #pragma unroll
        for (int j = 0; j < 16; ++j){
            float yn = fmaf((cur[j] - mu)*rs, ga, be);
            v = fmaf(v, 0.5f, yn);
            bool sp = (v >= 1.0f);
            if (do_store) op[(size_t)(t0v + j)*(BB*HCH)] = sp ? 1.0f : 0.0f;
            v = sp ? 0.0f : v;
        }
        #pragma unroll
        for (int j = 0; j < 16; ++j) cur[j] = nxt[j];
    }
}

extern "C" void kernel_launch(void* const* d_in, const int* in_sizes, int n_in,
                              void* d_out, int out_size){
    const float* x     = (const float*)d_in[0];
    const float* w     = (const float*)d_in[1];
    const float* bias  = (const float*)d_in[2];
    const float* gamma = (const float*)d_in[3];
    const float* beta  = (const float*)d_in[4];
    float* out = (float*)d_out;

    cudaFuncSetAttribute(prep_x_kernel, cudaFuncAttributeMaxDynamicSharedMemorySize, 3*CIN*132*2);
    cudaFuncSetAttribute(conv_mma_kernel, cudaFuncAttributeMaxDynamicSharedMemorySize, SMEM_CONV);

    prep_x_kernel<<<dim3(TT_/128, BB), 256, 3*CIN*132*2>>>(x);
    prep_w_kernel<<<384, 256>>>(w);
    conv_mma_kernel<<<dim3(TT_/128, 2, BB), 512, SMEM_CONV>>>(bias);
    bn_stats_kernel<<<512, 256>>>();
    lif_kernel<<<(BB*HCH*NCHUNK)/256, 256>>>(gamma, beta, out);
}